// round 2
// baseline (speedup 1.0000x reference)
#include <cuda_runtime.h>
#include <cstdint>

#define NB 32
#define NT 1024
#define ND 512
#define NU 64

// Scratch (device globals: no allocation allowed in kernel_launch)
__device__ float g_C[2ull * NB * ND * 128]; // x_s^T @ [w2|w3], 16.8 MB
__device__ float g_M[2ull * NB * ND * NU];  // per-branch M matrices, 8.4 MB
__device__ float g_E[2 * NB * NT];          // raw scores e
__device__ float g_W[2 * NB * NT];          // softmax weights ww

// ---- packed fp32x2 helpers (sm_103a FFMA2) ----
__device__ __forceinline__ void ffma2(unsigned long long& acc, unsigned long long a,
                                      unsigned long long b) {
    asm("fma.rn.f32x2 %0, %1, %2, %0;" : "+l"(acc) : "l"(a), "l"(b));
}
__device__ __forceinline__ unsigned long long pack2(float lo, float hi) {
    unsigned long long r;
    asm("mov.b64 %0, {%1, %2};" : "=l"(r) : "f"(lo), "f"(hi));
    return r;
}
__device__ __forceinline__ float2 unpack2(unsigned long long v) {
    float2 r;
    asm("mov.b64 {%0, %1}, %2;" : "=f"(r.x), "=f"(r.y) : "l"(v));
    return r;
}

// ============================================================
// K1: C[s][b] = X_s[b]^T @ [w2 | w3]   (D=512 x 128, K=T=1024)
// block tile 64(d) x 128(u), 256 threads, thread tile 8d x 4u
// accumulators packed along d (a-pairs direct from smem).
// ============================================================
__global__ void __launch_bounds__(256) k1_xtw(const float* __restrict__ x1,
                                              const float* __restrict__ x2,
                                              const float* __restrict__ w2,
                                              const float* __restrict__ w3) {
    __shared__ float Xs[32][64];
    __shared__ float Ws[32][128];
    const int dt = blockIdx.x;  // 0..7 (d tile)
    const int b = blockIdx.y;
    const int s = blockIdx.z;
    const float* __restrict__ X = s ? x2 : x1;
    const int tid = threadIdx.x;
    const int ux = tid & 31;  // u group (4 u's)
    const int dy = tid >> 5;  // d group (8 d's)
    const int d0 = dt * 64;

    unsigned long long acc[4][4];
#pragma unroll
    for (int i = 0; i < 4; i++)
#pragma unroll
        for (int j = 0; j < 4; j++) acc[i][j] = 0ull;

    for (int k0 = 0; k0 < NT; k0 += 32) {
        // X tile: 32 t-rows x 64 d (contiguous along d)
#pragma unroll
        for (int i = 0; i < 2; i++) {
            int f = tid + i * 256;
            int r = f >> 4, c = (f & 15) << 2;
            *(float4*)&Xs[r][c] =
                *(const float4*)(X + ((size_t)b * NT + k0 + r) * ND + d0 + c);
        }
        // W tile: 32 t-rows x 128 u ([w2 | w3])
#pragma unroll
        for (int i = 0; i < 4; i++) {
            int f = tid + i * 256;
            int r = f >> 5, c = f & 31;
            const float* src = (c < 16) ? (w2 + (size_t)(k0 + r) * NU + (c << 2))
                                        : (w3 + (size_t)(k0 + r) * NU + ((c - 16) << 2));
            *(float4*)&Ws[r][c << 2] = *(const float4*)src;
        }
        __syncthreads();
#pragma unroll
        for (int k = 0; k < 32; k++) {
            const ulonglong2 a01 = *(const ulonglong2*)&Xs[k][dy * 8];
            const ulonglong2 a23 = *(const ulonglong2*)&Xs[k][dy * 8 + 4];
            const float4 bv = *(const float4*)&Ws[k][ux * 4];
            unsigned long long av[4] = {a01.x, a01.y, a23.x, a23.y};
            unsigned long long bd[4] = {pack2(bv.x, bv.x), pack2(bv.y, bv.y),
                                        pack2(bv.z, bv.z), pack2(bv.w, bv.w)};
#pragma unroll
            for (int i = 0; i < 4; i++)
#pragma unroll
                for (int j = 0; j < 4; j++) ffma2(acc[i][j], av[i], bd[j]);
        }
        __syncthreads();
    }
    float* Cb = g_C + (size_t)(s * NB + b) * ND * 128;
#pragma unroll
    for (int i = 0; i < 4; i++) {
        int d = d0 + dy * 8 + i * 2;
#pragma unroll
        for (int j = 0; j < 4; j++) {
            float2 v = unpack2(acc[i][j]);
            int u = ux * 4 + j;
            Cb[(size_t)d * 128 + u] = v.x;
            Cb[(size_t)(d + 1) * 128 + u] = v.y;
        }
    }
}

// ============================================================
// K_prep: M[s][b][d][u] = C[1-s][b][d][u] + C[s][b][d][64+u] + w1[d][u]
// ============================================================
__global__ void __launch_bounds__(256) k_prep(const float* __restrict__ w1) {
    int i = blockIdx.x * 256 + threadIdx.x;  // over 2*NB*ND*NU = 2097152
    int u = i & 63;
    int d = (i >> 6) & (ND - 1);
    int sb = i >> 15;  // s*32+b
    int s = sb >> 5, b = sb & 31;
    float v = g_C[(((size_t)((1 - s) * NB + b) * ND + d) << 7) + u] +
              g_C[(((size_t)(s * NB + b) * ND + d) << 7) + 64 + u] + w1[d * NU + u];
    g_M[i] = v;
}

// ============================================================
// K2: e[s][b][t] = 10 * sum_u tanh( (X_s[b] @ M_s[b])[t,u] ) * we[u]
// block tile 128(t) x 64(u), K=D=512, 256 threads, thread tile 4t x 8u,
// accumulators packed along u (b-pairs direct from smem).
// ============================================================
__global__ void __launch_bounds__(256) k2_he(const float* __restrict__ x1,
                                             const float* __restrict__ x2,
                                             const float* __restrict__ we) {
    __shared__ float Xs[128][36];  // [t][k], padded row
    __shared__ float Ms[32][64];   // [k][u]
    __shared__ float wes[64];
    __shared__ float red[128][8];
    const int tt = blockIdx.x;  // 0..7 (t tile)
    const int b = blockIdx.y;
    const int s = blockIdx.z;
    const float* __restrict__ X = s ? x2 : x1;
    const int tid = threadIdx.x;
    const int ug = tid & 7;   // u group (8 u's)
    const int tg = tid >> 3;  // t group (4 t's)
    const int t0 = tt * 128;
    const int sb = s * NB + b;

    if (tid < 64) wes[tid] = we[tid];

    unsigned long long acc[4][4];
#pragma unroll
    for (int i = 0; i < 4; i++)
#pragma unroll
        for (int j = 0; j < 4; j++) acc[i][j] = 0ull;

    const float* __restrict__ Mb = g_M + (size_t)sb * ND * NU;

    for (int k0 = 0; k0 < ND; k0 += 32) {
#pragma unroll
        for (int i = 0; i < 4; i++) {
            int f = tid + i * 256;
            int t = f >> 3, kc = (f & 7) << 2;
            *(float4*)&Xs[t][kc] =
                *(const float4*)(X + ((size_t)b * NT + t0 + t) * ND + k0 + kc);
        }
#pragma unroll
        for (int i = 0; i < 2; i++) {
            int f = tid + i * 256;
            int r = f >> 4, c = (f & 15) << 2;
            *(float4*)&Ms[r][c] = *(const float4*)(Mb + (size_t)(k0 + r) * NU + c);
        }
        __syncthreads();
#pragma unroll
        for (int k = 0; k < 32; k++) {
            const ulonglong2 b01 = *(const ulonglong2*)&Ms[k][ug * 8];
            const ulonglong2 b23 = *(const ulonglong2*)&Ms[k][ug * 8 + 4];
            unsigned long long bv[4] = {b01.x, b01.y, b23.x, b23.y};
            unsigned long long ad[4];
#pragma unroll
            for (int i = 0; i < 4; i++) {
                float a = Xs[tg * 4 + i][k];
                ad[i] = pack2(a, a);
            }
#pragma unroll
            for (int i = 0; i < 4; i++)
#pragma unroll
                for (int j = 0; j < 4; j++) ffma2(acc[i][j], ad[i], bv[j]);
        }
        __syncthreads();
    }
    // epilogue: partial e per thread over its 8 u's, then reduce across ug
#pragma unroll
    for (int i = 0; i < 4; i++) {
        float p = 0.f;
#pragma unroll
        for (int j = 0; j < 4; j++) {
            float2 h = unpack2(acc[i][j]);
            int u = ug * 8 + j * 2;
            p += tanhf(h.x) * wes[u] + tanhf(h.y) * wes[u + 1];
        }
        red[tg * 4 + i][ug] = p;
    }
    __syncthreads();
    if (tid < 128) {
        float e = 0.f;
#pragma unroll
        for (int q = 0; q < 8; q++) e += red[tid][q];
        g_E[sb * NT + t0 + tid] = 10.0f * e;
    }
}

// ============================================================
// K3: softmax over T per (s,b):  ww = exp(e) / (sum(exp(e)) + 1e-7)
// (unstabilized, matching the reference exactly)
// ============================================================
__global__ void __launch_bounds__(256) k3_softmax() {
    const int sb = blockIdx.x;
    const int tid = threadIdx.x;
    __shared__ float ssum[8];
    float a[4];
    float lsum = 0.f;
#pragma unroll
    for (int i = 0; i < 4; i++) {
        a[i] = expf(g_E[sb * NT + tid + i * 256]);
        lsum += a[i];
    }
#pragma unroll
    for (int o = 16; o; o >>= 1) lsum += __shfl_xor_sync(0xffffffffu, lsum, o);
    if ((tid & 31) == 0) ssum[tid >> 5] = lsum;
    __syncthreads();
    if (tid == 0) {
        float sT = 0.f;
#pragma unroll
        for (int q = 0; q < 8; q++) sT += ssum[q];
        ssum[0] = 1.0f / (sT + 1e-7f);
    }
    __syncthreads();
    float inv = ssum[0];
#pragma unroll
    for (int i = 0; i < 4; i++) g_W[sb * NT + tid + i * 256] = a[i] * inv;
}

// ============================================================
// K4: out[s][b][t][d] = X_s[b][t][d] * ww[s][b][t]   (float4 streaming)
// ============================================================
__global__ void __launch_bounds__(256) k4_scale(const float* __restrict__ x1,
                                                const float* __restrict__ x2,
                                                float* __restrict__ out) {
    size_t f = (size_t)blockIdx.x * 256 + threadIdx.x;  // float4 index
    int d4 = (int)(f & 127);
    int t = (int)((f >> 7) & 1023);
    int sb = (int)(f >> 17);  // 0..63
    const float* __restrict__ X = (sb >= NB) ? x2 : x1;
    int b = sb & 31;
    float w = g_W[sb * NT + t];
    float4 v = *(const float4*)(X + ((size_t)b * NT + t) * ND + (d4 << 2));
    v.x *= w;
    v.y *= w;
    v.z *= w;
    v.w *= w;
    ((float4*)out)[f] = v;
}

extern "C" void kernel_launch(void* const* d_in, const int* in_sizes, int n_in,
                              void* d_out, int out_size) {
    const float* x1 = (const float*)d_in[0];
    const float* x2 = (const float*)d_in[1];
    const float* w1 = (const float*)d_in[2];
    const float* w2 = (const float*)d_in[3];
    const float* w3 = (const float*)d_in[4];
    const float* we = (const float*)d_in[5];
    float* out = (float*)d_out;

    dim3 g1(ND / 64, NB, 2);
    k1_xtw<<<g1, 256>>>(x1, x2, w2, w3);

    k_prep<<<(2 * NB * ND * NU) / 256, 256>>>(w1);

    dim3 g2(NT / 128, NB, 2);
    k2_he<<<g2, 256>>>(x1, x2, we);

    k3_softmax<<<2 * NB, 256>>>();

    k4_scale<<<(2u * NB * NT * (ND / 4)) / 256, 256>>>(x1, x2, out);
}

// round 4
// speedup vs baseline: 1.0819x; 1.0819x over previous
#include <cuda_runtime.h>
#include <cstdint>

#define NB 32
#define NT 1024
#define ND 512
#define NU 64

// -------- scratch (device globals) --------
__device__ float g_C[2ull * NB * ND * 128];  // X^T@[w2|w3] fp32  (16.8MB)
__device__ float g_M[64ull * ND * NU];       // [sb][d][u] fp32   (8.4MB)
__device__ float g_E[2 * NB * NT];
__device__ float g_W[2 * NB * NT];

// -------- helpers --------
__device__ __forceinline__ uint32_t smem_u32(const void* p) {
    uint32_t a;
    asm("{ .reg .u64 t; cvta.to.shared.u64 t, %1; cvt.u32.u64 %0, t; }" : "=r"(a) : "l"(p));
    return a;
}
__device__ __forceinline__ uint32_t tf32h(float x) {
    uint32_t r;
    asm("cvt.rna.tf32.f32 %0, %1;" : "=r"(r) : "f"(x));
    return r;
}
__device__ __forceinline__ void mma_tf32(float* c, const uint32_t* a, const uint32_t* b) {
    asm volatile(
        "mma.sync.aligned.m16n8k8.row.col.f32.tf32.tf32.f32 "
        "{%0,%1,%2,%3}, {%4,%5,%6,%7}, {%8,%9}, {%0,%1,%2,%3};"
        : "+f"(c[0]), "+f"(c[1]), "+f"(c[2]), "+f"(c[3])
        : "r"(a[0]), "r"(a[1]), "r"(a[2]), "r"(a[3]), "r"(b[0]), "r"(b[1]));
}
__device__ __forceinline__ void cp16(uint32_t dst, const void* src) {
    asm volatile("cp.async.cg.shared.global [%0], [%1], 16;" :: "r"(dst), "l"(src));
}
#define CP_COMMIT() asm volatile("cp.async.commit_group;" ::: "memory")
#define CP_WAIT1() asm volatile("cp.async.wait_group 1;" ::: "memory")
#define CP_WAIT0() asm volatile("cp.async.wait_group 0;" ::: "memory")

// ============================================================================
// K1: C[s][b] = X_s[b]^T @ [w2|w3]   M=128(d) N=128(u) K=1024(t)
// 8 warps (2M x 4N), warp tile 64x32, Kc=16 double-buffered cp.async.
// smem fp32, stride 136 (conflict-free transposed fragment reads).
// ============================================================================
#define K1S 136
__global__ void __launch_bounds__(256, 2) k1_xtw(const float* __restrict__ x1,
                                                 const float* __restrict__ x2,
                                                 const float* __restrict__ w2,
                                                 const float* __restrict__ w3) {
    __shared__ __align__(16) float sA[2][16][K1S];  // [t][d]
    __shared__ __align__(16) float sB[2][16][K1S];  // [t][u]
    const int tid = threadIdx.x, wid = tid >> 5, lane = tid & 31;
    const int gid = lane >> 2, tig = lane & 3;
    const int dt = blockIdx.x, b = blockIdx.y, s = blockIdx.z;
    const float* __restrict__ X = s ? x2 : x1;
    const int d0 = dt * 128;
    const int wm = (wid >> 2) * 64, wn = (wid & 3) * 32;

    float acc[4][4][4];
#pragma unroll
    for (int i = 0; i < 4; i++)
#pragma unroll
        for (int j = 0; j < 4; j++)
#pragma unroll
            for (int q = 0; q < 4; q++) acc[i][j][q] = 0.f;

    const uint32_t aB = smem_u32(&sA[0][0][0]);
    const uint32_t bB = smem_u32(&sB[0][0][0]);
    const uint32_t bufBytes = 16 * K1S * 4;

    auto issue = [&](int ch, int bi) {
        const int k0 = ch * 16;
#pragma unroll
        for (int it = 0; it < 2; it++) {
            int ff = tid + it * 256;
            int r = ff >> 5, c = (ff & 31) * 4;
            cp16(aB + bi * bufBytes + (uint32_t)(r * K1S + c) * 4,
                 X + ((size_t)b * NT + k0 + r) * ND + d0 + c);
        }
#pragma unroll
        for (int it = 0; it < 2; it++) {
            int ff = tid + it * 256;
            int r = ff >> 5, c = (ff & 31) * 4;
            const float* src = (c < 64) ? (w2 + (size_t)(k0 + r) * NU + c)
                                        : (w3 + (size_t)(k0 + r) * NU + (c - 64));
            cp16(bB + bi * bufBytes + (uint32_t)(r * K1S + c) * 4, src);
        }
        CP_COMMIT();
    };

    issue(0, 0);
    for (int ch = 0; ch < 64; ch++) {
        if (ch + 1 < 64) {
            issue(ch + 1, (ch + 1) & 1);
            CP_WAIT1();
        } else {
            CP_WAIT0();
        }
        __syncthreads();
        const float(*A)[K1S] = sA[ch & 1];
        const float(*B)[K1S] = sB[ch & 1];
#pragma unroll
        for (int ks = 0; ks < 2; ks++) {
            const int kt = ks * 8;
            uint32_t bh[4][2], bl[4][2];
#pragma unroll
            for (int ni = 0; ni < 4; ni++) {
                float v0 = B[kt + tig][wn + ni * 8 + gid];
                float v1 = B[kt + tig + 4][wn + ni * 8 + gid];
                bh[ni][0] = tf32h(v0);
                bl[ni][0] = __float_as_uint(v0 - __uint_as_float(bh[ni][0]));
                bh[ni][1] = tf32h(v1);
                bl[ni][1] = __float_as_uint(v1 - __uint_as_float(bh[ni][1]));
            }
#pragma unroll
            for (int mi = 0; mi < 4; mi++) {
                const int dm = wm + mi * 16 + gid;
                float u0 = A[kt + tig][dm];
                float u1 = A[kt + tig][dm + 8];
                float u2 = A[kt + tig + 4][dm];
                float u3 = A[kt + tig + 4][dm + 8];
                uint32_t ah[4], al[4];
                ah[0] = tf32h(u0); al[0] = __float_as_uint(u0 - __uint_as_float(ah[0]));
                ah[1] = tf32h(u1); al[1] = __float_as_uint(u1 - __uint_as_float(ah[1]));
                ah[2] = tf32h(u2); al[2] = __float_as_uint(u2 - __uint_as_float(ah[2]));
                ah[3] = tf32h(u3); al[3] = __float_as_uint(u3 - __uint_as_float(ah[3]));
#pragma unroll
                for (int ni = 0; ni < 4; ni++) {
                    mma_tf32(acc[mi][ni], ah, bh[ni]);
                    mma_tf32(acc[mi][ni], al, bh[ni]);
                    mma_tf32(acc[mi][ni], ah, bl[ni]);
                }
            }
        }
        __syncthreads();
    }
    float* dst = g_C + (size_t)(s * NB + b) * ND * 128 + (size_t)d0 * 128;
#pragma unroll
    for (int mi = 0; mi < 4; mi++) {
        int r0 = wm + mi * 16 + gid, r1 = r0 + 8;
#pragma unroll
        for (int ni = 0; ni < 4; ni++) {
            int col = wn + ni * 8 + 2 * tig;
            *(float2*)(dst + (size_t)r0 * 128 + col) =
                make_float2(acc[mi][ni][0], acc[mi][ni][1]);
            *(float2*)(dst + (size_t)r1 * 128 + col) =
                make_float2(acc[mi][ni][2], acc[mi][ni][3]);
        }
    }
}

// ============================================================================
// K_prep: M[sb][d][u] = C[1-s][b][d][u] + C[s][b][d][64+u] + w1[d][u]
// ============================================================================
__global__ void __launch_bounds__(256) k_prep(const float* __restrict__ w1) {
    size_t i = (size_t)blockIdx.x * 256 + threadIdx.x;  // 2,097,152 total
    int u = (int)(i & 63);
    int d = (int)((i >> 6) & (ND - 1));
    int sb = (int)(i >> 15);
    int s = sb >> 5, b = sb & 31;
    float v = g_C[(((size_t)((1 - s) * NB + b) * ND + d) << 7) + u] +
              g_C[(((size_t)sb * ND + d) << 7) + 64 + u] + w1[d * NU + u];
    g_M[i] = v;
}

// ============================================================================
// K2: e = 10*sum_u tanh(X@M)*we    M=128(t) N=64(u) K=512(d)
// 8 warps (4M x 2N), warp tile 32x32, Kc=16 double-buffered.
// ============================================================================
#define K2AS 20
#define K2BS 72
__global__ void __launch_bounds__(256, 2) k2_he(const float* __restrict__ x1,
                                                const float* __restrict__ x2,
                                                const float* __restrict__ we) {
    __shared__ __align__(16) float sA[2][128][K2AS];  // [t][d]
    __shared__ __align__(16) float sB[2][16][K2BS];   // [d][u]
    __shared__ float wes[64];
    __shared__ float red[128][2];
    const int tid = threadIdx.x, wid = tid >> 5, lane = tid & 31;
    const int gid = lane >> 2, tig = lane & 3;
    const int tt = blockIdx.x, b = blockIdx.y, s = blockIdx.z;
    const float* __restrict__ X = s ? x2 : x1;
    const int t0 = tt * 128, sb = s * NB + b;
    const int wm = (wid >> 1) * 32, wn = (wid & 1) * 32;

    if (tid < 64) wes[tid] = we[tid];

    float acc[2][4][4];
#pragma unroll
    for (int i = 0; i < 2; i++)
#pragma unroll
        for (int j = 0; j < 4; j++)
#pragma unroll
            for (int q = 0; q < 4; q++) acc[i][j][q] = 0.f;

    const uint32_t aB = smem_u32(&sA[0][0][0]);
    const uint32_t bB = smem_u32(&sB[0][0][0]);
    const float* __restrict__ Mb = g_M + (size_t)sb * ND * NU;

    auto issue = [&](int ch, int bi) {
        const int k0 = ch * 16;
#pragma unroll
        for (int it = 0; it < 2; it++) {
            int ff = tid + it * 256;
            int r = ff >> 2, c = (ff & 3) * 4;
            cp16(aB + (uint32_t)(bi * 128 * K2AS + r * K2AS + c) * 4,
                 X + ((size_t)b * NT + t0 + r) * ND + k0 + c);
        }
        {
            int r = tid >> 4, c = (tid & 15) * 4;
            cp16(bB + (uint32_t)(bi * 16 * K2BS + r * K2BS + c) * 4,
                 Mb + (size_t)(k0 + r) * NU + c);
        }
        CP_COMMIT();
    };

    issue(0, 0);
    for (int ch = 0; ch < 32; ch++) {
        if (ch + 1 < 32) {
            issue(ch + 1, (ch + 1) & 1);
            CP_WAIT1();
        } else {
            CP_WAIT0();
        }
        __syncthreads();
        const float(*A)[K2AS] = sA[ch & 1];
        const float(*B)[K2BS] = sB[ch & 1];
#pragma unroll
        for (int ks = 0; ks < 2; ks++) {
            const int kd = ks * 8;
            uint32_t bh[4][2], bl[4][2];
#pragma unroll
            for (int ni = 0; ni < 4; ni++) {
                float v0 = B[kd + tig][wn + ni * 8 + gid];
                float v1 = B[kd + tig + 4][wn + ni * 8 + gid];
                bh[ni][0] = tf32h(v0);
                bl[ni][0] = __float_as_uint(v0 - __uint_as_float(bh[ni][0]));
                bh[ni][1] = tf32h(v1);
                bl[ni][1] = __float_as_uint(v1 - __uint_as_float(bh[ni][1]));
            }
#pragma unroll
            for (int mi = 0; mi < 2; mi++) {
                const int tr = wm + mi * 16 + gid;
                float u0 = A[tr][kd + tig];
                float u1 = A[tr + 8][kd + tig];
                float u2 = A[tr][kd + tig + 4];
                float u3 = A[tr + 8][kd + tig + 4];
                uint32_t ah[4], al[4];
                ah[0] = tf32h(u0); al[0] = __float_as_uint(u0 - __uint_as_float(ah[0]));
                ah[1] = tf32h(u1); al[1] = __float_as_uint(u1 - __uint_as_float(ah[1]));
                ah[2] = tf32h(u2); al[2] = __float_as_uint(u2 - __uint_as_float(ah[2]));
                ah[3] = tf32h(u3); al[3] = __float_as_uint(u3 - __uint_as_float(ah[3]));
#pragma unroll
                for (int ni = 0; ni < 4; ni++) {
                    mma_tf32(acc[mi][ni], ah, bh[ni]);
                    mma_tf32(acc[mi][ni], al, bh[ni]);
                    mma_tf32(acc[mi][ni], ah, bl[ni]);
                }
            }
        }
        __syncthreads();
    }
    // epilogue: e(t) = 10 * sum_u tanh(h[t,u]) * we[u]
#pragma unroll
    for (int mi = 0; mi < 2; mi++) {
        int r0 = wm + mi * 16 + gid, r1 = r0 + 8;
        float p0 = 0.f, p1 = 0.f;
#pragma unroll
        for (int ni = 0; ni < 4; ni++) {
            int u = wn + ni * 8 + 2 * tig;
            p0 += tanhf(acc[mi][ni][0]) * wes[u] + tanhf(acc[mi][ni][1]) * wes[u + 1];
            p1 += tanhf(acc[mi][ni][2]) * wes[u] + tanhf(acc[mi][ni][3]) * wes[u + 1];
        }
        p0 += __shfl_xor_sync(0xffffffffu, p0, 1);
        p0 += __shfl_xor_sync(0xffffffffu, p0, 2);
        p1 += __shfl_xor_sync(0xffffffffu, p1, 1);
        p1 += __shfl_xor_sync(0xffffffffu, p1, 2);
        if (tig == 0) {
            red[r0][wid & 1] = p0;
            red[r1][wid & 1] = p1;
        }
    }
    __syncthreads();
    if (tid < 128) {
        g_E[sb * NT + t0 + tid] = 10.0f * (red[tid][0] + red[tid][1]);
    }
}

// ============================================================================
// K3: softmax over T per (s,b) (unstabilized, matches reference)
// ============================================================================
__global__ void __launch_bounds__(256) k3_softmax() {
    const int sb = blockIdx.x, tid = threadIdx.x;
    __shared__ float ssum[8];
    float a[4], lsum = 0.f;
#pragma unroll
    for (int i = 0; i < 4; i++) {
        a[i] = expf(g_E[sb * NT + tid + i * 256]);
        lsum += a[i];
    }
#pragma unroll
    for (int o = 16; o; o >>= 1) lsum += __shfl_xor_sync(0xffffffffu, lsum, o);
    if ((tid & 31) == 0) ssum[tid >> 5] = lsum;
    __syncthreads();
    if (tid == 0) {
        float sT = 0.f;
#pragma unroll
        for (int q = 0; q < 8; q++) sT += ssum[q];
        ssum[0] = 1.0f / (sT + 1e-7f);
    }
    __syncthreads();
    float inv = ssum[0];
#pragma unroll
    for (int i = 0; i < 4; i++) g_W[sb * NT + tid + i * 256] = a[i] * inv;
}

// ============================================================================
// K4: out = X * ww  (float4 streaming)
// ============================================================================
__global__ void __launch_bounds__(256) k4_scale(const float* __restrict__ x1,
                                                const float* __restrict__ x2,
                                                float* __restrict__ out) {
    size_t f = (size_t)blockIdx.x * 256 + threadIdx.x;
    int d4 = (int)(f & 127);
    int t = (int)((f >> 7) & 1023);
    int sb = (int)(f >> 17);
    const float* __restrict__ X = (sb >= NB) ? x2 : x1;
    int b = sb & 31;
    float w = g_W[sb * NT + t];
    float4 v = *(const float4*)(X + ((size_t)b * NT + t) * ND + (d4 << 2));
    v.x *= w; v.y *= w; v.z *= w; v.w *= w;
    ((float4*)out)[f] = v;
}

extern "C" void kernel_launch(void* const* d_in, const int* in_sizes, int n_in,
                              void* d_out, int out_size) {
    const float* x1 = (const float*)d_in[0];
    const float* x2 = (const float*)d_in[1];
    const float* w1 = (const float*)d_in[2];
    const float* w2 = (const float*)d_in[3];
    const float* w3 = (const float*)d_in[4];
    const float* we = (const float*)d_in[5];
    float* out = (float*)d_out;

    dim3 g1(ND / 128, NB, 2);
    k1_xtw<<<g1, 256>>>(x1, x2, w2, w3);

    k_prep<<<(2 * NB * ND * NU) / 256, 256>>>(w1);

    dim3 g2(NT / 128, NB, 2);
    k2_he<<<g2, 256>>>(x1, x2, we);

    k3_softmax<<<2 * NB, 256>>>();

    k4_scale<<<(2u * NB * NT * (ND / 4)) / 256, 256>>>(x1, x2, out);
}

// round 5
// speedup vs baseline: 2.0255x; 1.8722x over previous
#include <cuda_runtime.h>
#include <cstdint>

#define NB 32
#define NT 1024
#define ND 512
#define NU 64

// -------- scratch (device globals) --------
__device__ float g_C[2ull * NB * ND * 128];  // X^T@[w2|w3] fp32  (16.8MB)
__device__ float g_M[64ull * ND * NU];       // [sb][d][u] fp32   (8.4MB)
__device__ float g_E[2 * NB * NT];
__device__ float g_W[2 * NB * NT];

// -------- helpers --------
__device__ __forceinline__ uint32_t smem_u32(const void* p) {
    uint32_t a;
    asm("{ .reg .u64 t; cvta.to.shared.u64 t, %1; cvt.u32.u64 %0, t; }" : "=r"(a) : "l"(p));
    return a;
}
// pack (x0,x1) -> f16x2 hi-reg (lo half = x0), and residual lo-reg
__device__ __forceinline__ void split_pair(float x0, float x1, uint32_t& hi, uint32_t& lo) {
    asm("cvt.rn.f16x2.f32 %0, %1, %2;" : "=r"(hi) : "f"(x1), "f"(x0));
    float h0, h1;
    asm("{ .reg .b16 a, b; mov.b32 {a, b}, %2; cvt.f32.f16 %0, a; cvt.f32.f16 %1, b; }"
        : "=f"(h0), "=f"(h1) : "r"(hi));
    float l0 = x0 - h0, l1 = x1 - h1;
    asm("cvt.rn.f16x2.f32 %0, %1, %2;" : "=r"(lo) : "f"(l1), "f"(l0));
}
__device__ __forceinline__ void mma_f16(float* c, const uint32_t* a, const uint32_t* b) {
    asm volatile(
        "mma.sync.aligned.m16n8k16.row.col.f32.f16.f16.f32 "
        "{%0,%1,%2,%3}, {%4,%5,%6,%7}, {%8,%9}, {%0,%1,%2,%3};"
        : "+f"(c[0]), "+f"(c[1]), "+f"(c[2]), "+f"(c[3])
        : "r"(a[0]), "r"(a[1]), "r"(a[2]), "r"(a[3]), "r"(b[0]), "r"(b[1]));
}
__device__ __forceinline__ void cp16(uint32_t dst, const void* src) {
    asm volatile("cp.async.cg.shared.global [%0], [%1], 16;" :: "r"(dst), "l"(src));
}
#define CP_COMMIT() asm volatile("cp.async.commit_group;" ::: "memory")
#define CP_WAIT1() asm volatile("cp.async.wait_group 1;" ::: "memory")
#define CP_WAIT0() asm volatile("cp.async.wait_group 0;" ::: "memory")

// ============================================================================
// K1: C[s][b] = X_s[b]^T @ [w2|w3]   M=128(d) N=128(u) K=1024(t)
// 8 warps (2M x 4N), warp tile 64x32, Kc=16 double-buffered cp.async.
// fp32 smem, stride 132 (conflict-free k-pair fragment reads).
// fp16 split-2, 3-pass m16n8k16.
// ============================================================================
#define K1S 132
__global__ void __launch_bounds__(256, 2) k1_xtw(const float* __restrict__ x1,
                                                 const float* __restrict__ x2,
                                                 const float* __restrict__ w2,
                                                 const float* __restrict__ w3) {
    __shared__ __align__(16) float sA[2][16][K1S];  // [t][d]
    __shared__ __align__(16) float sB[2][16][K1S];  // [t][u]
    const int tid = threadIdx.x, wid = tid >> 5, lane = tid & 31;
    const int gid = lane >> 2, tig = lane & 3;
    const int dt = blockIdx.x, b = blockIdx.y, s = blockIdx.z;
    const float* __restrict__ X = s ? x2 : x1;
    const int d0 = dt * 128;
    const int wm = (wid >> 2) * 64, wn = (wid & 3) * 32;

    float acc[4][4][4];
#pragma unroll
    for (int i = 0; i < 4; i++)
#pragma unroll
        for (int j = 0; j < 4; j++)
#pragma unroll
            for (int q = 0; q < 4; q++) acc[i][j][q] = 0.f;

    const uint32_t aB = smem_u32(&sA[0][0][0]);
    const uint32_t bB = smem_u32(&sB[0][0][0]);
    const uint32_t bufBytes = 16 * K1S * 4;

    auto issue = [&](int ch, int bi) {
        const int k0 = ch * 16;
#pragma unroll
        for (int it = 0; it < 2; it++) {
            int ff = tid + it * 256;
            int r = ff >> 5, c = (ff & 31) * 4;
            cp16(aB + bi * bufBytes + (uint32_t)(r * K1S + c) * 4,
                 X + ((size_t)b * NT + k0 + r) * ND + d0 + c);
        }
#pragma unroll
        for (int it = 0; it < 2; it++) {
            int ff = tid + it * 256;
            int r = ff >> 5, c = (ff & 31) * 4;
            const float* src = (c < 64) ? (w2 + (size_t)(k0 + r) * NU + c)
                                        : (w3 + (size_t)(k0 + r) * NU + (c - 64));
            cp16(bB + bi * bufBytes + (uint32_t)(r * K1S + c) * 4, src);
        }
        CP_COMMIT();
    };

    issue(0, 0);
    for (int ch = 0; ch < 64; ch++) {
        if (ch + 1 < 64) {
            issue(ch + 1, (ch + 1) & 1);
            CP_WAIT1();
        } else {
            CP_WAIT0();
        }
        __syncthreads();
        const float(*A)[K1S] = sA[ch & 1];
        const float(*B)[K1S] = sB[ch & 1];
        // B fragments (k = t dim, rows 2tig..)
        uint32_t bh[4][2], bl[4][2];
#pragma unroll
        for (int ni = 0; ni < 4; ni++) {
            const int un = wn + ni * 8 + gid;
            split_pair(B[2 * tig][un], B[2 * tig + 1][un], bh[ni][0], bl[ni][0]);
            split_pair(B[2 * tig + 8][un], B[2 * tig + 9][un], bh[ni][1], bl[ni][1]);
        }
#pragma unroll
        for (int mi = 0; mi < 4; mi++) {
            const int dm = wm + mi * 16 + gid;
            uint32_t ah[4], al[4];
            split_pair(A[2 * tig][dm], A[2 * tig + 1][dm], ah[0], al[0]);
            split_pair(A[2 * tig][dm + 8], A[2 * tig + 1][dm + 8], ah[1], al[1]);
            split_pair(A[2 * tig + 8][dm], A[2 * tig + 9][dm], ah[2], al[2]);
            split_pair(A[2 * tig + 8][dm + 8], A[2 * tig + 9][dm + 8], ah[3], al[3]);
#pragma unroll
            for (int ni = 0; ni < 4; ni++) {
                mma_f16(acc[mi][ni], ah, bh[ni]);
                mma_f16(acc[mi][ni], al, bh[ni]);
                mma_f16(acc[mi][ni], ah, bl[ni]);
            }
        }
        __syncthreads();
    }
    float* dst = g_C + (size_t)(s * NB + b) * ND * 128 + (size_t)d0 * 128;
#pragma unroll
    for (int mi = 0; mi < 4; mi++) {
        int r0 = wm + mi * 16 + gid, r1 = r0 + 8;
#pragma unroll
        for (int ni = 0; ni < 4; ni++) {
            int col = wn + ni * 8 + 2 * tig;
            *(float2*)(dst + (size_t)r0 * 128 + col) =
                make_float2(acc[mi][ni][0], acc[mi][ni][1]);
            *(float2*)(dst + (size_t)r1 * 128 + col) =
                make_float2(acc[mi][ni][2], acc[mi][ni][3]);
        }
    }
}

// ============================================================================
// K_prep: M[sb][d][u] = C[1-s][b][d][u] + C[s][b][d][64+u] + w1[d][u]
// ============================================================================
__global__ void __launch_bounds__(256) k_prep(const float* __restrict__ w1) {
    size_t i = (size_t)blockIdx.x * 256 + threadIdx.x;  // 2,097,152 total
    int u = (int)(i & 63);
    int d = (int)((i >> 6) & (ND - 1));
    int sb = (int)(i >> 15);
    int s = sb >> 5, b = sb & 31;
    float v = g_C[(((size_t)((1 - s) * NB + b) * ND + d) << 7) + u] +
              g_C[(((size_t)sb * ND + d) << 7) + 64 + u] + w1[d * NU + u];
    g_M[i] = v;
}

// ============================================================================
// K2: e = 10*sum_u tanh(X@M)*we    M=128(t) N=64(u) K=512(d)
// 8 warps (4M x 2N), warp tile 32x32, Kc=16 double-buffered, fp16 3-pass.
// ============================================================================
#define K2AS 20
#define K2BS 68
__global__ void __launch_bounds__(256, 2) k2_he(const float* __restrict__ x1,
                                                const float* __restrict__ x2,
                                                const float* __restrict__ we) {
    __shared__ __align__(16) float sA[2][128][K2AS];  // [t][d]
    __shared__ __align__(16) float sB[2][16][K2BS];   // [d][u]
    __shared__ float wes[64];
    __shared__ float red[128][2];
    const int tid = threadIdx.x, wid = tid >> 5, lane = tid & 31;
    const int gid = lane >> 2, tig = lane & 3;
    const int tt = blockIdx.x, b = blockIdx.y, s = blockIdx.z;
    const float* __restrict__ X = s ? x2 : x1;
    const int t0 = tt * 128, sb = s * NB + b;
    const int wm = (wid >> 1) * 32, wn = (wid & 1) * 32;

    if (tid < 64) wes[tid] = we[tid];

    float acc[2][4][4];
#pragma unroll
    for (int i = 0; i < 2; i++)
#pragma unroll
        for (int j = 0; j < 4; j++)
#pragma unroll
            for (int q = 0; q < 4; q++) acc[i][j][q] = 0.f;

    const uint32_t aB = smem_u32(&sA[0][0][0]);
    const uint32_t bB = smem_u32(&sB[0][0][0]);
    const float* __restrict__ Mb = g_M + (size_t)sb * ND * NU;

    auto issue = [&](int ch, int bi) {
        const int k0 = ch * 16;
#pragma unroll
        for (int it = 0; it < 2; it++) {
            int ff = tid + it * 256;
            int r = ff >> 2, c = (ff & 3) * 4;
            cp16(aB + (uint32_t)(bi * 128 * K2AS + r * K2AS + c) * 4,
                 X + ((size_t)b * NT + t0 + r) * ND + k0 + c);
        }
        {
            int r = tid >> 4, c = (tid & 15) * 4;
            cp16(bB + (uint32_t)(bi * 16 * K2BS + r * K2BS + c) * 4,
                 Mb + (size_t)(k0 + r) * NU + c);
        }
        CP_COMMIT();
    };

    issue(0, 0);
    for (int ch = 0; ch < 32; ch++) {
        if (ch + 1 < 32) {
            issue(ch + 1, (ch + 1) & 1);
            CP_WAIT1();
        } else {
            CP_WAIT0();
        }
        __syncthreads();
        const float(*A)[K2AS] = sA[ch & 1];
        const float(*B)[K2BS] = sB[ch & 1];
        uint32_t bh[4][2], bl[4][2];
#pragma unroll
        for (int ni = 0; ni < 4; ni++) {
            const int un = wn + ni * 8 + gid;
            split_pair(B[2 * tig][un], B[2 * tig + 1][un], bh[ni][0], bl[ni][0]);
            split_pair(B[2 * tig + 8][un], B[2 * tig + 9][un], bh[ni][1], bl[ni][1]);
        }
#pragma unroll
        for (int mi = 0; mi < 2; mi++) {
            const int tr = wm + mi * 16 + gid;
            uint32_t ah[4], al[4];
            {
                float2 v = *(const float2*)&A[tr][2 * tig];
                split_pair(v.x, v.y, ah[0], al[0]);
            }
            {
                float2 v = *(const float2*)&A[tr + 8][2 * tig];
                split_pair(v.x, v.y, ah[1], al[1]);
            }
            {
                float2 v = *(const float2*)&A[tr][2 * tig + 8];
                split_pair(v.x, v.y, ah[2], al[2]);
            }
            {
                float2 v = *(const float2*)&A[tr + 8][2 * tig + 8];
                split_pair(v.x, v.y, ah[3], al[3]);
            }
#pragma unroll
            for (int ni = 0; ni < 4; ni++) {
                mma_f16(acc[mi][ni], ah, bh[ni]);
                mma_f16(acc[mi][ni], al, bh[ni]);
                mma_f16(acc[mi][ni], ah, bl[ni]);
            }
        }
        __syncthreads();
    }
    // epilogue: e(t) = 10 * sum_u tanh(h[t,u]) * we[u]
#pragma unroll
    for (int mi = 0; mi < 2; mi++) {
        int r0 = wm + mi * 16 + gid, r1 = r0 + 8;
        float p0 = 0.f, p1 = 0.f;
#pragma unroll
        for (int ni = 0; ni < 4; ni++) {
            int u = wn + ni * 8 + 2 * tig;
            p0 += tanhf(acc[mi][ni][0]) * wes[u] + tanhf(acc[mi][ni][1]) * wes[u + 1];
            p1 += tanhf(acc[mi][ni][2]) * wes[u] + tanhf(acc[mi][ni][3]) * wes[u + 1];
        }
        p0 += __shfl_xor_sync(0xffffffffu, p0, 1);
        p0 += __shfl_xor_sync(0xffffffffu, p0, 2);
        p1 += __shfl_xor_sync(0xffffffffu, p1, 1);
        p1 += __shfl_xor_sync(0xffffffffu, p1, 2);
        if (tig == 0) {
            red[r0][wid & 1] = p0;
            red[r1][wid & 1] = p1;
        }
    }
    __syncthreads();
    if (tid < 128) {
        g_E[sb * NT + t0 + tid] = 10.0f * (red[tid][0] + red[tid][1]);
    }
}

// ============================================================================
// K3: softmax over T per (s,b) (unstabilized, matches reference)
// ============================================================================
__global__ void __launch_bounds__(256) k3_softmax() {
    const int sb = blockIdx.x, tid = threadIdx.x;
    __shared__ float ssum[8];
    float a[4], lsum = 0.f;
#pragma unroll
    for (int i = 0; i < 4; i++) {
        a[i] = expf(g_E[sb * NT + tid + i * 256]);
        lsum += a[i];
    }
#pragma unroll
    for (int o = 16; o; o >>= 1) lsum += __shfl_xor_sync(0xffffffffu, lsum, o);
    if ((tid & 31) == 0) ssum[tid >> 5] = lsum;
    __syncthreads();
    if (tid == 0) {
        float sT = 0.f;
#pragma unroll
        for (int q = 0; q < 8; q++) sT += ssum[q];
        ssum[0] = 1.0f / (sT + 1e-7f);
    }
    __syncthreads();
    float inv = ssum[0];
#pragma unroll
    for (int i = 0; i < 4; i++) g_W[sb * NT + tid + i * 256] = a[i] * inv;
}

// ============================================================================
// K4: out = X * ww  (float4 streaming)
// ============================================================================
__global__ void __launch_bounds__(256) k4_scale(const float* __restrict__ x1,
                                                const float* __restrict__ x2,
                                                float* __restrict__ out) {
    size_t f = (size_t)blockIdx.x * 256 + threadIdx.x;
    int d4 = (int)(f & 127);
    int t = (int)((f >> 7) & 1023);
    int sb = (int)(f >> 17);
    const float* __restrict__ X = (sb >= NB) ? x2 : x1;
    int b = sb & 31;
    float w = g_W[sb * NT + t];
    float4 v = *(const float4*)(X + ((size_t)b * NT + t) * ND + (d4 << 2));
    v.x *= w; v.y *= w; v.z *= w; v.w *= w;
    ((float4*)out)[f] = v;
}

extern "C" void kernel_launch(void* const* d_in, const int* in_sizes, int n_in,
                              void* d_out, int out_size) {
    const float* x1 = (const float*)d_in[0];
    const float* x2 = (const float*)d_in[1];
    const float* w1 = (const float*)d_in[2];
    const float* w2 = (const float*)d_in[3];
    const float* w3 = (const float*)d_in[4];
    const float* we = (const float*)d_in[5];
    float* out = (float*)d_out;

    dim3 g1(ND / 128, NB, 2);
    k1_xtw<<<g1, 256>>>(x1, x2, w2, w3);

    k_prep<<<(2 * NB * ND * NU) / 256, 256>>>(w1);

    dim3 g2(NT / 128, NB, 2);
    k2_he<<<g2, 256>>>(x1, x2, we);

    k3_softmax<<<2 * NB, 256>>>();

    k4_scale<<<(2u * NB * NT * (ND / 4)) / 256, 256>>>(x1, x2, out);
}